// round 1
// baseline (speedup 1.0000x reference)
#include <cuda_runtime.h>
#include <math.h>

#define BATCH 2
#define SEQ   2048
#define DIM   2048
#define NHEAD 8
#define HDIM  256
#define EDIM  (NHEAD * HDIM)   // 2048
#define MROWS (BATCH * SEQ)    // 4096

// ---------------- scratch (device globals: no cudaMalloc allowed) ----------
__device__ float g_Q[(size_t)MROWS * EDIM];                 // 33.5 MB
__device__ float g_K[(size_t)MROWS * EDIM];
__device__ float g_V[(size_t)MROWS * EDIM];
__device__ float g_O[(size_t)MROWS * EDIM];
__device__ float g_S[(size_t)BATCH * NHEAD * SEQ * SEQ];    // 268 MB scores/probs

// ---------------- generic strided-batched SGEMM ----------------------------
// C[m][n] = alpha * sum_k A[m][k] * (TRANSB ? B[n][k] : B[k][n])
// CAUSAL:   skip blocks fully above diagonal, mask elements n > m with -1e30
// CAUSAL_K: limit K loop to m0 + BM (PV: P is zero/unwritten beyond that)
#define BM 128
#define BN 128
#define BK 8

template<bool TRANSB, bool CAUSAL, bool CAUSAL_K>
__global__ __launch_bounds__(256)
void gemm_tile(const float* __restrict__ Ag, const float* __restrict__ Bg,
               float* __restrict__ Cg,
               int M, int N, int K, int lda, int ldb, int ldc,
               int batch_inner,
               long sa_out, long sa_in, long sb_out, long sb_in,
               long sc_out, long sc_in, float alpha)
{
    const int z  = blockIdx.z;
    const int zo = z / batch_inner, zi = z % batch_inner;
    const float* A = Ag + zo * sa_out + zi * sa_in;
    const float* B = Bg + zo * sb_out + zi * sb_in;
    float*       C = Cg + zo * sc_out + zi * sc_in;

    const int m0 = blockIdx.y * BM;
    const int n0 = blockIdx.x * BN;
    if (CAUSAL && n0 > m0) return;   // block fully above diagonal

    __shared__ __align__(16) float As[BK][BM + 4];
    __shared__ __align__(16) float Bs[BK][BN + 4];

    const int tid = threadIdx.x;
    const int tx = tid & 15;       // 0..15 -> 8 output cols (tx*4 and 64+tx*4)
    const int ty = tid >> 4;       // 0..15 -> 8 output rows

    float acc[8][8];
#pragma unroll
    for (int i = 0; i < 8; i++)
#pragma unroll
        for (int j = 0; j < 8; j++) acc[i][j] = 0.f;

    // global A load: row = tid/2 (0..127), 4 k's at (tid&1)*4
    const int arow = tid >> 1;
    const int acol = (tid & 1) * 4;
    const float* Aptr = A + (long)(m0 + arow) * lda + acol;

    int kend = K;
    if (CAUSAL_K) { int ke = m0 + BM; kend = ke < K ? ke : K; }

    const float* Bptr;
    int brow, bcol;
    if (TRANSB) { brow = tid >> 1; bcol = (tid & 1) * 4;
                  Bptr = B + (long)(n0 + brow) * ldb + bcol; }
    else        { brow = tid >> 5; bcol = (tid & 31) * 4;
                  Bptr = B + (long)brow * ldb + n0 + bcol; }

    for (int k0 = 0; k0 < kend; k0 += BK) {
        float4 av = *(const float4*)(Aptr + k0);
        float4 bv;
        if (TRANSB) bv = *(const float4*)(Bptr + k0);
        else        bv = *(const float4*)(Bptr + (long)k0 * ldb);

        __syncthreads();              // previous iter's smem reads done
        As[acol + 0][arow] = av.x;
        As[acol + 1][arow] = av.y;
        As[acol + 2][arow] = av.z;
        As[acol + 3][arow] = av.w;
        if (TRANSB) {
            Bs[bcol + 0][brow] = bv.x;
            Bs[bcol + 1][brow] = bv.y;
            Bs[bcol + 2][brow] = bv.z;
            Bs[bcol + 3][brow] = bv.w;
        } else {
            *(float4*)&Bs[brow][bcol] = bv;
        }
        __syncthreads();

#pragma unroll
        for (int kk = 0; kk < BK; kk++) {
            float4 a0 = *(const float4*)&As[kk][ty * 4];
            float4 a1 = *(const float4*)&As[kk][64 + ty * 4];
            float4 b0 = *(const float4*)&Bs[kk][tx * 4];
            float4 b1 = *(const float4*)&Bs[kk][64 + tx * 4];
            float ar[8] = {a0.x, a0.y, a0.z, a0.w, a1.x, a1.y, a1.z, a1.w};
            float br[8] = {b0.x, b0.y, b0.z, b0.w, b1.x, b1.y, b1.z, b1.w};
#pragma unroll
            for (int i = 0; i < 8; i++)
#pragma unroll
                for (int j = 0; j < 8; j++) acc[i][j] += ar[i] * br[j];
        }
    }

    // epilogue (vectorized float4 stores; optional causal mask)
#pragma unroll
    for (int i = 0; i < 8; i++) {
        const int row = m0 + ((i < 4) ? (ty * 4 + i) : (64 + ty * 4 + i - 4));
        float* crow = C + (long)row * ldc;
#pragma unroll
        for (int half = 0; half < 2; half++) {
            const int cbase = n0 + (half ? 64 + tx * 4 : tx * 4);
            float4 v;
            float* pv = &v.x;
#pragma unroll
            for (int j = 0; j < 4; j++) {
                float val = acc[i][half * 4 + j] * alpha;
                if (CAUSAL && (cbase + j) > row) val = -1e30f;
                pv[j] = val;
            }
            *(float4*)(crow + cbase) = v;
        }
    }
}

// ---------------- warp reductions ------------------------------------------
__device__ __forceinline__ float warp_sum(float v) {
#pragma unroll
    for (int o = 16; o; o >>= 1) v += __shfl_xor_sync(0xffffffffu, v, o);
    return v;
}
__device__ __forceinline__ float warp_max(float v) {
#pragma unroll
    for (int o = 16; o; o >>= 1) v = fmaxf(v, __shfl_xor_sync(0xffffffffu, v, o));
    return v;
}

// ---------------- fused RMSNorm + RoPE (in place on Q or K) -----------------
__global__ __launch_bounds__(HDIM)
void rmsnorm_rope(float* __restrict__ X, const float* __restrict__ w,
                  const int* __restrict__ pos_ids)
{
    const int s = blockIdx.x, b = blockIdx.y, t = threadIdx.x;
    __shared__ float buf[HDIM];
    __shared__ float red[8];

    const int half = HDIM / 2;                   // 128
    const int fi = (t < half) ? t : t - half;
    // inv_freq = 10000^{-fi/128}; fp64 for accuracy of angle at large pos
    const double inv = exp(-(double)fi * (9.210340371976184 / 128.0));
    const double ang = (double)pos_ids[s] * inv;
    const float cs = (float)cos(ang);
    const float sn = (float)sin(ang);
    const float wt = w[t];

    float* base = X + ((long)(b * SEQ + s)) * EDIM;
    const int wid = t >> 5, lane = t & 31;

    for (int h = 0; h < NHEAD; h++) {
        float* v = base + h * HDIM;
        const float x = v[t];
        float ss = warp_sum(x * x);
        __syncthreads();                          // red/buf from prev h consumed
        if (lane == 0) red[wid] = ss;
        __syncthreads();
        float tot = 0.f;
#pragma unroll
        for (int r = 0; r < 8; r++) tot += red[r];

        const float xn = x * rsqrtf(tot * (1.0f / HDIM) + 1e-6f) * wt;
        buf[t] = xn;
        __syncthreads();

        float out;
        if (t < half) out = xn * cs - buf[t + half] * sn;   // rx1
        else          out = xn * cs + buf[t - half] * sn;   // rx2
        v[t] = out;
    }
}

// ---------------- causal row softmax (in place on g_S) ----------------------
__global__ __launch_bounds__(256)
void softmax_causal(float* __restrict__ Sc)
{
    const int q  = blockIdx.x;
    const int bh = blockIdx.y;
    float* row = Sc + ((long)bh * SEQ + q) * SEQ;
    const int W = (((q >> 7) + 1) << 7);          // roundup128(q+1)

    const int tid = threadIdx.x;
    const int wid = tid >> 5, lane = tid & 31;
    __shared__ float red[8];

    float x[8];
    float m = -1e30f;
#pragma unroll
    for (int i = 0; i < 8; i++) {
        const int idx = tid + i * 256;
        x[i] = (idx < W) ? row[idx] : -1e30f;
        m = fmaxf(m, x[i]);
    }
    m = warp_max(m);
    if (lane == 0) red[wid] = m;
    __syncthreads();
    float M = -1e30f;
#pragma unroll
    for (int r = 0; r < 8; r++) M = fmaxf(M, red[r]);

    float ssum = 0.f;
#pragma unroll
    for (int i = 0; i < 8; i++) {
        x[i] = __expf(x[i] - M);                  // masked -> exp(-huge) = 0
        ssum += x[i];
    }
    ssum = warp_sum(ssum);
    __syncthreads();
    if (lane == 0) red[wid] = ssum;
    __syncthreads();
    float tot = 0.f;
#pragma unroll
    for (int r = 0; r < 8; r++) tot += red[r];
    const float invs = 1.0f / tot;

#pragma unroll
    for (int i = 0; i < 8; i++) {
        const int idx = tid + i * 256;
        if (idx < W) row[idx] = x[i] * invs;
    }
}

// ---------------- launcher --------------------------------------------------
extern "C" void kernel_launch(void* const* d_in, const int* in_sizes, int n_in,
                              void* d_out, int out_size)
{
    const float* x    = (const float*)d_in[0];
    const int*   pos  = (const int*)  d_in[1];
    const float* Wq   = (const float*)d_in[2];
    const float* Wk   = (const float*)d_in[3];
    const float* Wv   = (const float*)d_in[4];
    const float* Wo   = (const float*)d_in[5];
    const float* qw   = (const float*)d_in[6];
    const float* kw   = (const float*)d_in[7];
    float* out = (float*)d_out;

    float *Q, *K, *V, *O, *Sc;
    cudaGetSymbolAddress((void**)&Q,  g_Q);
    cudaGetSymbolAddress((void**)&K,  g_K);
    cudaGetSymbolAddress((void**)&V,  g_V);
    cudaGetSymbolAddress((void**)&O,  g_O);
    cudaGetSymbolAddress((void**)&Sc, g_S);

    const dim3 blk(256);
    const long SS = (long)SEQ * SEQ;

    // 1) QKV projections: [4096,2048] x [2048,2048]^T
    const dim3 g1(EDIM / BN, MROWS / BM, 1);
    gemm_tile<true, false, false><<<g1, blk>>>(x, Wq, Q, MROWS, EDIM, DIM,
        DIM, DIM, EDIM, 1, 0, 0, 0, 0, 0, 0, 1.0f);
    gemm_tile<true, false, false><<<g1, blk>>>(x, Wk, K, MROWS, EDIM, DIM,
        DIM, DIM, EDIM, 1, 0, 0, 0, 0, 0, 0, 1.0f);
    gemm_tile<true, false, false><<<g1, blk>>>(x, Wv, V, MROWS, EDIM, DIM,
        DIM, DIM, EDIM, 1, 0, 0, 0, 0, 0, 0, 1.0f);

    // 2) RMSNorm + RoPE on Q and K
    rmsnorm_rope<<<dim3(SEQ, BATCH), HDIM>>>(Q, qw, pos);
    rmsnorm_rope<<<dim3(SEQ, BATCH), HDIM>>>(K, kw, pos);

    // 3) scores = Q K^T * scale, causal masked  (batch = B*H, block-skip upper)
    const dim3 g2(SEQ / BN, SEQ / BM, BATCH * NHEAD);
    gemm_tile<true, true, false><<<g2, blk>>>(Q, K, Sc, SEQ, SEQ, HDIM,
        EDIM, EDIM, SEQ,
        NHEAD, (long)SEQ * EDIM, HDIM, (long)SEQ * EDIM, HDIM,
        (long)NHEAD * SS, SS, 0.0625f);

    // 4) causal softmax (in place)
    softmax_causal<<<dim3(SEQ, BATCH * NHEAD), blk>>>(Sc);

    // 5) O = P V   (NN, causal K-limit per row-block)
    const dim3 g3(HDIM / BN, SEQ / BM, BATCH * NHEAD);
    gemm_tile<false, false, true><<<g3, blk>>>(Sc, V, O, SEQ, HDIM, SEQ,
        SEQ, EDIM, EDIM,
        NHEAD, (long)NHEAD * SS, SS, (long)SEQ * EDIM, HDIM,
        (long)SEQ * EDIM, HDIM, 1.0f);

    // 6) out = O Wo^T
    gemm_tile<true, false, false><<<g1, blk>>>(O, Wo, out, MROWS, DIM, EDIM,
        EDIM, EDIM, DIM, 1, 0, 0, 0, 0, 0, 0, 1.0f);
}

// round 3
// speedup vs baseline: 2.0556x; 2.0556x over previous
#include <cuda_runtime.h>
#include <math.h>
#include <stdint.h>

#define BATCH 2
#define SEQ   2048
#define DIM   2048
#define NHEAD 8
#define HDIM  256
#define EDIM  (NHEAD * HDIM)   // 2048
#define MROWS (BATCH * SEQ)    // 4096

// ---------------- scratch (device globals: no cudaMalloc allowed) ----------
__device__ float g_Q [(size_t)MROWS * EDIM];
__device__ float g_K [(size_t)MROWS * EDIM];
__device__ float g_V [(size_t)MROWS * EDIM];
__device__ float g_Vt[(size_t)MROWS * EDIM];
__device__ float g_O [(size_t)MROWS * EDIM];
__device__ float g_S [(size_t)BATCH * NHEAD * SEQ * SEQ];   // 268 MB
__device__ float g_sin[SEQ * (HDIM / 2)];
__device__ float g_cos[SEQ * (HDIM / 2)];

// ---------------- helpers ----------------------------------------------------
__device__ __forceinline__ uint32_t s2u(const void* p) {
    return (uint32_t)__cvta_generic_to_shared(p);
}
__device__ __forceinline__ void cpa16(uint32_t s, const void* g) {
    asm volatile("cp.async.cg.shared.global [%0], [%1], 16;" :: "r"(s), "l"(g));
}
#define CP_COMMIT() asm volatile("cp.async.commit_group;" ::: "memory")
#define CP_WAIT1()  asm volatile("cp.async.wait_group 1;" ::: "memory")

// bf16x2 split: pack two floats into hi (bf16x2) and residual lo (bf16x2).
// element 0 (f.x) in lower 16 bits (matches mma fragment element order).
__device__ __forceinline__ void pack_split(float2 f, uint32_t& hi, uint32_t& lo) {
    uint32_t h;
    asm("cvt.rn.bf16x2.f32 %0, %1, %2;" : "=r"(h) : "f"(f.y), "f"(f.x));
    float fyh = __uint_as_float(h & 0xffff0000u);
    float fxh = __uint_as_float(h << 16);
    asm("cvt.rn.bf16x2.f32 %0, %1, %2;" : "=r"(lo) : "f"(f.y - fyh), "f"(f.x - fxh));
    hi = h;
}

__device__ __forceinline__ void mma16816(float* c, const uint32_t* a, const uint32_t* b) {
    asm volatile("mma.sync.aligned.m16n8k16.row.col.f32.bf16.bf16.f32 "
        "{%0,%1,%2,%3},{%4,%5,%6,%7},{%8,%9},{%0,%1,%2,%3};"
        : "+f"(c[0]), "+f"(c[1]), "+f"(c[2]), "+f"(c[3])
        : "r"(a[0]), "r"(a[1]), "r"(a[2]), "r"(a[3]), "r"(b[0]), "r"(b[1]));
}

// ---------------- bf16x3-split tensor-core GEMM ------------------------------
// C[m][n] = alpha * sum_k A[m][k] * B[n][k]    (A, B both K-major fp32)
#define BM 128
#define BN 128
#define BK 16
#define NS 3
#define ROWF 20                                  // padded row: 16 data + 4 pad floats
#define TILE_F (128 * ROWF)                      // floats per operand tile
#define STAGE_F (2 * TILE_F)                     // A then B
#define GEMM_SMEM (NS * STAGE_F * 4)             // 61440 B

template<bool CAUSAL, bool CAUSAL_K>
__global__ void __launch_bounds__(256)
gemm_tc(const float* __restrict__ Ag, const float* __restrict__ Bg,
        float* __restrict__ Cg,
        int K, int lda, int ldb, int ldc, int batch_inner,
        long sa_out, long sa_in, long sb_out, long sb_in,
        long sc_out, long sc_in, float alpha)
{
    const int m0 = blockIdx.y * BM;
    const int n0 = blockIdx.x * BN;
    if (CAUSAL && n0 > m0 + BM - 1) return;

    const int z = blockIdx.z, zo = z / batch_inner, zi = z % batch_inner;
    const float* A = Ag + zo * sa_out + zi * sa_in;
    const float* B = Bg + zo * sb_out + zi * sb_in;
    float*       C = Cg + zo * sc_out + zi * sc_in;

    extern __shared__ __align__(16) float smem[];
    const uint32_t sbase = s2u(smem);

    const int tid = threadIdx.x, wid = tid >> 5, lane = tid & 31;
    const int wm = wid >> 2, wn = wid & 3;           // warp grid 2 x 4
    const int warp_row = wm * 64, warp_col = wn * 32;
    const int r  = lane >> 2;                        // fragment row
    const int cq = (lane & 3) * 2;                   // fragment col pair

    int kend = K;
    if (CAUSAL_K) { int ke = m0 + BM; kend = ke < K ? ke : K; }
    const int nk = kend / BK;

    const float* Abase = A + (long)m0 * lda;
    const float* Bbase = B + (long)n0 * ldb;

    auto load_stage = [&](int stage) {
        const int slot = stage % NS;
        const int k0 = stage * BK;
        const uint32_t sa = sbase + slot * STAGE_F * 4;
        const uint32_t sb = sa + TILE_F * 4;
#pragma unroll
        for (int i = 0; i < 2; i++) {
            int v = tid + i * 256;                 // 512 chunks: 128 rows x 4
            int rr = v >> 2, cc = v & 3;
            cpa16(sa + rr * (ROWF * 4) + cc * 16, Abase + (long)rr * lda + k0 + cc * 4);
        }
#pragma unroll
        for (int i = 0; i < 2; i++) {
            int v = tid + i * 256;
            int rr = v >> 2, cc = v & 3;
            cpa16(sb + rr * (ROWF * 4) + cc * 16, Bbase + (long)rr * ldb + k0 + cc * 4);
        }
        CP_COMMIT();
    };

    float acc[4][4][4];
#pragma unroll
    for (int i = 0; i < 4; i++)
#pragma unroll
        for (int j = 0; j < 4; j++)
#pragma unroll
            for (int e = 0; e < 4; e++) acc[i][j][e] = 0.f;

    load_stage(0);
    if (nk > 1) load_stage(1); else CP_COMMIT();

    for (int it = 0; it < nk; it++) {
        CP_WAIT1();
        __syncthreads();

        if (it + 2 < nk) load_stage(it + 2);

        const int slot = it % NS;
        const float* As = smem + slot * STAGE_F;
        const float* Bs = As + TILE_F;

        // B fragments for 4 n-tiles (hi + lo)
        uint32_t bh[4][2], bl[4][2];
#pragma unroll
        for (int j = 0; j < 4; j++) {
            const float* bp = Bs + (warp_col + j * 8 + (lane >> 2)) * ROWF + cq;
            pack_split(*(const float2*)(bp),     bh[j][0], bl[j][0]);
            pack_split(*(const float2*)(bp + 8), bh[j][1], bl[j][1]);
        }

#pragma unroll
        for (int i = 0; i < 4; i++) {
            const float* ap = As + (warp_row + i * 16 + r) * ROWF + cq;
            uint32_t ah[4], al[4];
            pack_split(*(const float2*)(ap),                 ah[0], al[0]);
            pack_split(*(const float2*)(ap + 8 * ROWF),      ah[1], al[1]);
            pack_split(*(const float2*)(ap + 8),             ah[2], al[2]);
            pack_split(*(const float2*)(ap + 8 * ROWF + 8),  ah[3], al[3]);
#pragma unroll
            for (int j = 0; j < 4; j++) {
                mma16816(acc[i][j], ah, bh[j]);   // hi*hi
                mma16816(acc[i][j], ah, bl[j]);   // hi*lo
                mma16816(acc[i][j], al, bh[j]);   // lo*hi
            }
        }
        __syncthreads();
    }

    // ---------------- epilogue ----------------
#pragma unroll
    for (int i = 0; i < 4; i++) {
#pragma unroll
        for (int j = 0; j < 4; j++) {
            const int col = n0 + warp_col + j * 8 + cq;
            const int row0 = m0 + warp_row + i * 16 + r;
            const int row1 = row0 + 8;
            float2 v0, v1;
            v0.x = acc[i][j][0] * alpha; v0.y = acc[i][j][1] * alpha;
            v1.x = acc[i][j][2] * alpha; v1.y = acc[i][j][3] * alpha;
            if (CAUSAL) {
                if (col     > row0) v0.x = -1e30f;
                if (col + 1 > row0) v0.y = -1e30f;
                if (col     > row1) v1.x = -1e30f;
                if (col + 1 > row1) v1.y = -1e30f;
            }
            *(float2*)(C + (long)row0 * ldc + col) = v0;
            *(float2*)(C + (long)row1 * ldc + col) = v1;
        }
    }
}

// ---------------- warp reductions ------------------------------------------
__device__ __forceinline__ float warp_sum(float v) {
#pragma unroll
    for (int o = 16; o; o >>= 1) v += __shfl_xor_sync(0xffffffffu, v, o);
    return v;
}
__device__ __forceinline__ float warp_max(float v) {
#pragma unroll
    for (int o = 16; o; o >>= 1) v = fmaxf(v, __shfl_xor_sync(0xffffffffu, v, o));
    return v;
}

// ---------------- RoPE tables (fp64, once) ----------------------------------
__global__ void __launch_bounds__(256)
rope_tables(const int* __restrict__ pos) {
    const int i = blockIdx.x * 256 + threadIdx.x;     // SEQ*128 threads
    const int s = i >> 7, fi = i & 127;
    const double inv = exp(-(double)fi * (9.210340371976184 / 128.0));
    const double ang = (double)pos[s] * inv;
    g_sin[i] = (float)sin(ang);
    g_cos[i] = (float)cos(ang);
}

// ---------------- fused RMSNorm + RoPE (one block per (h,s,b)) --------------
__global__ void __launch_bounds__(HDIM)
rmsnorm_rope(float* __restrict__ X, const float* __restrict__ w)
{
    const int h = blockIdx.x, s = blockIdx.y, b = blockIdx.z, t = threadIdx.x;
    __shared__ float buf[HDIM];
    __shared__ float red[8];

    const int half = HDIM / 2;
    const int fi = (t < half) ? t : t - half;
    const float cs = g_cos[s * half + fi];
    const float sn = g_sin[s * half + fi];

    float* v = X + ((long)(b * SEQ + s)) * EDIM + h * HDIM;
    const float x = v[t];
    const int wid = t >> 5, lane = t & 31;

    float ss = warp_sum(x * x);
    if (lane == 0) red[wid] = ss;
    __syncthreads();
    float tot = 0.f;
#pragma unroll
    for (int rr = 0; rr < 8; rr++) tot += red[rr];

    const float xn = x * rsqrtf(tot * (1.0f / HDIM) + 1e-6f) * w[t];
    buf[t] = xn;
    __syncthreads();

    float out;
    if (t < half) out = xn * cs - buf[t + half] * sn;
    else          out = xn * cs + buf[t - half] * sn;
    v[t] = out;
}

// ---------------- V transpose: per (b,h)  Vt[d][s] = V[s][d] -----------------
__global__ void __launch_bounds__(256)
transpose_v(const float* __restrict__ V, float* __restrict__ Vt)
{
    __shared__ float tile[32][33];
    const int bh = blockIdx.z;
    const int b = bh / NHEAD, h = bh % NHEAD;
    const int s0 = blockIdx.x * 32, d0 = blockIdx.y * 32;
    const int tx = threadIdx.x & 31, ty = threadIdx.x >> 5;   // 32 x 8

    const float* src = V + (long)b * SEQ * EDIM + h * HDIM;
#pragma unroll
    for (int i = ty; i < 32; i += 8)
        tile[i][tx] = src[(long)(s0 + i) * EDIM + d0 + tx];
    __syncthreads();
    float* dst = Vt + ((long)bh * HDIM + d0) * SEQ + s0;
#pragma unroll
    for (int i = ty; i < 32; i += 8)
        dst[(long)i * SEQ + tx] = tile[tx][i];
}

// ---------------- causal row softmax (in place) ------------------------------
__global__ void __launch_bounds__(256)
softmax_causal(float* __restrict__ Sc)
{
    const int q  = blockIdx.x;
    const int bh = blockIdx.y;
    float* row = Sc + ((long)bh * SEQ + q) * SEQ;
    const int W = (((q >> 7) + 1) << 7);

    const int tid = threadIdx.x;
    const int wid = tid >> 5, lane = tid & 31;
    __shared__ float red[8];

    float x[8];
    float m = -1e30f;
#pragma unroll
    for (int i = 0; i < 8; i++) {
        const int idx = tid + i * 256;
        x[i] = (idx < W) ? row[idx] : -1e30f;
        m = fmaxf(m, x[i]);
    }
    m = warp_max(m);
    if (lane == 0) red[wid] = m;
    __syncthreads();
    float M = -1e30f;
#pragma unroll
    for (int rr = 0; rr < 8; rr++) M = fmaxf(M, red[rr]);

    float ssum = 0.f;
#pragma unroll
    for (int i = 0; i < 8; i++) { x[i] = __expf(x[i] - M); ssum += x[i]; }
    ssum = warp_sum(ssum);
    __syncthreads();
    if (lane == 0) red[wid] = ssum;
    __syncthreads();
    float tot = 0.f;
#pragma unroll
    for (int rr = 0; rr < 8; rr++) tot += red[rr];
    const float invs = 1.0f / tot;

#pragma unroll
    for (int i = 0; i < 8; i++) {
        const int idx = tid + i * 256;
        if (idx < W) row[idx] = x[i] * invs;
    }
}

// ---------------- launcher ---------------------------------------------------
extern "C" void kernel_launch(void* const* d_in, const int* in_sizes, int n_in,
                              void* d_out, int out_size)
{
    const float* x   = (const float*)d_in[0];
    const int*   pos = (const int*)  d_in[1];
    const float* Wq  = (const float*)d_in[2];
    const float* Wk  = (const float*)d_in[3];
    const float* Wv  = (const float*)d_in[4];
    const float* Wo  = (const float*)d_in[5];
    const float* qw  = (const float*)d_in[6];
    const float* kw  = (const float*)d_in[7];
    float* out = (float*)d_out;

    float *Q, *K, *V, *Vt, *O, *Sc;
    cudaGetSymbolAddress((void**)&Q,  g_Q);
    cudaGetSymbolAddress((void**)&K,  g_K);
    cudaGetSymbolAddress((void**)&V,  g_V);
    cudaGetSymbolAddress((void**)&Vt, g_Vt);
    cudaGetSymbolAddress((void**)&O,  g_O);
    cudaGetSymbolAddress((void**)&Sc, g_S);

    cudaFuncSetAttribute(gemm_tc<false, false>,
        cudaFuncAttributeMaxDynamicSharedMemorySize, GEMM_SMEM);
    cudaFuncSetAttribute(gemm_tc<true, false>,
        cudaFuncAttributeMaxDynamicSharedMemorySize, GEMM_SMEM);
    cudaFuncSetAttribute(gemm_tc<false, true>,
        cudaFuncAttributeMaxDynamicSharedMemorySize, GEMM_SMEM);

    const dim3 blk(256);
    const long SS = (long)SEQ * SEQ;

    rope_tables<<<(SEQ * (HDIM / 2)) / 256, 256>>>(pos);

    // 1) QKV projections: [4096 x 2048] = [4096 x 2048] * [2048 x 2048]^T
    const dim3 g1(EDIM / BN, MROWS / BM, 1);
    gemm_tc<false, false><<<g1, blk, GEMM_SMEM>>>(x, Wq, Q, DIM, DIM, DIM, EDIM,
        1, 0, 0, 0, 0, 0, 0, 1.0f);
    gemm_tc<false, false><<<g1, blk, GEMM_SMEM>>>(x, Wk, K, DIM, DIM, DIM, EDIM,
        1, 0, 0, 0, 0, 0, 0, 1.0f);
    gemm_tc<false, false><<<g1, blk, GEMM_SMEM>>>(x, Wv, V, DIM, DIM, DIM, EDIM,
        1, 0, 0, 0, 0, 0, 0, 1.0f);

    // 2) RMSNorm + RoPE on Q and K
    rmsnorm_rope<<<dim3(NHEAD, SEQ, BATCH), HDIM>>>(Q, qw);
    rmsnorm_rope<<<dim3(NHEAD, SEQ, BATCH), HDIM>>>(K, kw);

    // 2b) transpose V per head -> Vt [bh][d][s]
    transpose_v<<<dim3(SEQ / 32, HDIM / 32, BATCH * NHEAD), 256>>>(V, Vt);

    // 3) scores = Q K^T * scale (causal-masked, upper blocks skipped)
    const dim3 g2(SEQ / BN, SEQ / BM, BATCH * NHEAD);
    gemm_tc<true, false><<<g2, blk, GEMM_SMEM>>>(Q, K, Sc, HDIM, EDIM, EDIM, SEQ,
        NHEAD, (long)SEQ * EDIM, HDIM, (long)SEQ * EDIM, HDIM,
        (long)NHEAD * SS, SS, 0.0625f);

    // 4) causal softmax (in place)
    softmax_causal<<<dim3(SEQ, BATCH * NHEAD), blk>>>(Sc);

    // 5) O = P V   (K-limited to m0+128 per row-block)
    const dim3 g3(HDIM / BN, SEQ / BM, BATCH * NHEAD);
    gemm_tc<false, true><<<g3, blk, GEMM_SMEM>>>(Sc, Vt, O, SEQ, SEQ, SEQ, EDIM,
        NHEAD, (long)NHEAD * SS, SS,
        (long)NHEAD * HDIM * SEQ, (long)HDIM * SEQ,
        (long)SEQ * EDIM, HDIM, 1.0f);

    // 6) out = O Wo^T
    gemm_tc<false, false><<<g1, blk, GEMM_SMEM>>>(O, Wo, out, EDIM, EDIM, EDIM, DIM,
        1, 0, 0, 0, 0, 0, 0, 1.0f);
}

// round 4
// speedup vs baseline: 2.5125x; 1.2223x over previous
#include <cuda_runtime.h>
#include <math.h>
#include <stdint.h>

#define BATCH 2
#define SEQ   2048
#define DIM   2048
#define NHEAD 8
#define HDIM  256
#define EDIM  (NHEAD * HDIM)   // 2048
#define MROWS (BATCH * SEQ)    // 4096

// ---------------- scratch (device globals: no cudaMalloc allowed) ----------
__device__ float g_Q [(size_t)MROWS * EDIM];
__device__ float g_K [(size_t)MROWS * EDIM];
__device__ float g_V [(size_t)MROWS * EDIM];
__device__ float g_Vt[(size_t)MROWS * EDIM];
__device__ float g_O [(size_t)MROWS * EDIM];
__device__ float g_S [(size_t)BATCH * NHEAD * SEQ * SEQ];   // 268 MB
__device__ float g_sin[SEQ * (HDIM / 2)];
__device__ float g_cos[SEQ * (HDIM / 2)];

// ---------------- helpers ----------------------------------------------------
__device__ __forceinline__ uint32_t s2u(const void* p) {
    return (uint32_t)__cvta_generic_to_shared(p);
}

// bf16x2 split: two floats -> hi bf16x2 + residual lo bf16x2 (x in low 16).
__device__ __forceinline__ void pack_split(float2 f, uint32_t& hi, uint32_t& lo) {
    uint32_t h;
    asm("cvt.rn.bf16x2.f32 %0, %1, %2;" : "=r"(h) : "f"(f.y), "f"(f.x));
    float fyh = __uint_as_float(h & 0xffff0000u);
    float fxh = __uint_as_float(h << 16);
    asm("cvt.rn.bf16x2.f32 %0, %1, %2;" : "=r"(lo) : "f"(f.y - fyh), "f"(f.x - fxh));
    hi = h;
}

__device__ __forceinline__ void mma16816(float* c, const uint32_t* a, const uint32_t* b) {
    asm volatile("mma.sync.aligned.m16n8k16.row.col.f32.bf16.bf16.f32 "
        "{%0,%1,%2,%3},{%4,%5,%6,%7},{%8,%9},{%0,%1,%2,%3};"
        : "+f"(c[0]), "+f"(c[1]), "+f"(c[2]), "+f"(c[3])
        : "r"(a[0]), "r"(a[1]), "r"(a[2]), "r"(a[3]), "r"(b[0]), "r"(b[1]));
}

#define LDSM4(R, addr)                                                          \
    asm volatile("ldmatrix.sync.aligned.m8n8.x4.shared.b16 {%0,%1,%2,%3}, [%4];"\
        : "=r"((R)[0]), "=r"((R)[1]), "=r"((R)[2]), "=r"((R)[3]) : "r"(addr))

#define STS64(addr, r0, r1)                                                     \
    asm volatile("st.shared.v2.b32 [%0], {%1,%2};" :: "r"(addr), "r"(r0), "r"(r1))

// chunk swizzle for a 128x16 bf16 tile stored as 16B chunks (row, half-of-k16)
// conflict-free for both STS.64 stores and ldmatrix loads.
__device__ __forceinline__ uint32_t chunkoff(int row, int half) {
    const int line = row >> 2;
    const int cp = ((row & 3) << 1) | half;
    return (uint32_t)(line * 128 + ((cp ^ (line & 7)) << 4));
}

// ---------------- bf16x3-split tensor-core GEMM ------------------------------
// C[m][n] = alpha * sum_k A[m][k] * B[n][k]    (A, B both K-major fp32)
#define BM 128
#define BN 128
#define BK 16
#define STG 16384          // stage bytes: 4 tiles (A_hi, A_lo, B_hi, B_lo) x 4KB
#define T_AHI 0
#define T_ALO 4096
#define T_BHI 8192
#define T_BLO 12288

template<bool CAUSAL, bool CAUSAL_K>
__global__ void __launch_bounds__(256, 2)
gemm_tc(const float* __restrict__ Ag, const float* __restrict__ Bg,
        float* __restrict__ Cg,
        int K, int lda, int ldb, int ldc, int batch_inner,
        long sa_out, long sa_in, long sb_out, long sb_in,
        long sc_out, long sc_in, float alpha)
{
    const int m0 = blockIdx.y * BM;
    const int n0 = blockIdx.x * BN;
    if (CAUSAL && n0 > m0 + BM - 1) return;

    const int z = blockIdx.z, zo = z / batch_inner, zi = z % batch_inner;
    const float* A = Ag + zo * sa_out + zi * sa_in;
    const float* B = Bg + zo * sb_out + zi * sb_in;
    float*       C = Cg + zo * sc_out + zi * sc_in;

    __shared__ __align__(128) char smem[2 * STG];
    const uint32_t sbase = s2u(smem);

    const int tid = threadIdx.x, wid = tid >> 5, lane = tid & 31;
    const int wm = wid >> 2, wn = wid & 3;           // warp grid 2 x 4
    const int warp_row = wm * 64, warp_col = wn * 32;

    int kend = K;
    if (CAUSAL_K) { int ke = m0 + BM; kend = ke < K ? ke : K; }
    const int nk = kend / BK;

    const float* Abase = A + (long)m0 * lda;
    const float* Bbase = B + (long)n0 * ldb;

    // ldg/sts per-thread geometry: element (row = tid/4 + i*64, 4 cols at (tid&3)*4)
    const int grow = tid >> 2, gcq = tid & 3;
    const uint32_t stoff0 = chunkoff(grow,      gcq >> 1) + (gcq & 1) * 8;
    const uint32_t stoff1 = chunkoff(grow + 64, gcq >> 1) + (gcq & 1) * 8;

    // ldmatrix per-thread geometry
    const int mat = lane >> 3;
    const int lrow = ((mat & 1) << 3) | (lane & 7);
    const int lhalf = mat >> 1;
    uint32_t aoff[4];
#pragma unroll
    for (int i = 0; i < 4; i++)
        aoff[i] = chunkoff(warp_row + i * 16 + lrow, lhalf);
    const int bj = mat >> 1, bhh = mat & 1;
    const uint32_t boff0 = chunkoff(warp_col + bj * 8 + (lane & 7), bhh);
    const uint32_t boff1 = chunkoff(warp_col + 16 + bj * 8 + (lane & 7), bhh);

    float4 rA0, rA1, rB0, rB1;
    auto ldg = [&](int stage) {
        const long k0 = (long)stage * BK + gcq * 4;
        rA0 = *(const float4*)(Abase + (long)grow * lda + k0);
        rA1 = *(const float4*)(Abase + (long)(grow + 64) * lda + k0);
        rB0 = *(const float4*)(Bbase + (long)grow * ldb + k0);
        rB1 = *(const float4*)(Bbase + (long)(grow + 64) * ldb + k0);
    };
    auto sts = [&](int slot) {
        const uint32_t s0 = sbase + slot * STG;
        uint32_t h0, l0, h1, l1;
        pack_split(make_float2(rA0.x, rA0.y), h0, l0);
        pack_split(make_float2(rA0.z, rA0.w), h1, l1);
        STS64(s0 + T_AHI + stoff0, h0, h1);
        STS64(s0 + T_ALO + stoff0, l0, l1);
        pack_split(make_float2(rA1.x, rA1.y), h0, l0);
        pack_split(make_float2(rA1.z, rA1.w), h1, l1);
        STS64(s0 + T_AHI + stoff1, h0, h1);
        STS64(s0 + T_ALO + stoff1, l0, l1);
        pack_split(make_float2(rB0.x, rB0.y), h0, l0);
        pack_split(make_float2(rB0.z, rB0.w), h1, l1);
        STS64(s0 + T_BHI + stoff0, h0, h1);
        STS64(s0 + T_BLO + stoff0, l0, l1);
        pack_split(make_float2(rB1.x, rB1.y), h0, l0);
        pack_split(make_float2(rB1.z, rB1.w), h1, l1);
        STS64(s0 + T_BHI + stoff1, h0, h1);
        STS64(s0 + T_BLO + stoff1, l0, l1);
    };

    float acc[4][4][4];
#pragma unroll
    for (int i = 0; i < 4; i++)
#pragma unroll
        for (int j = 0; j < 4; j++)
#pragma unroll
            for (int e = 0; e < 4; e++) acc[i][j][e] = 0.f;

    ldg(0);
    sts(0);
    if (nk > 1) ldg(1);
    __syncthreads();

    for (int it = 0; it < nk; it++) {
        const uint32_t s0 = sbase + (it & 1) * STG;

        uint32_t bhr[8], blr[8];
        LDSM4(bhr + 0, s0 + T_BHI + boff0);
        LDSM4(bhr + 4, s0 + T_BHI + boff1);
        LDSM4(blr + 0, s0 + T_BLO + boff0);
        LDSM4(blr + 4, s0 + T_BLO + boff1);

#pragma unroll
        for (int i = 0; i < 4; i++) {
            uint32_t ah[4], al[4];
            LDSM4(ah, s0 + T_AHI + aoff[i]);
            LDSM4(al, s0 + T_ALO + aoff[i]);
#pragma unroll
            for (int j = 0; j < 4; j++) {
                mma16816(acc[i][j], ah, &bhr[j * 2]);   // hi*hi
                mma16816(acc[i][j], ah, &blr[j * 2]);   // hi*lo
                mma16816(acc[i][j], al, &bhr[j * 2]);   // lo*hi
            }
        }

        if (it + 1 < nk) sts((it + 1) & 1);   // writes other slot (readers synced)
        if (it + 2 < nk) ldg(it + 2);         // refill regs after STS consumed them
        __syncthreads();
    }

    // ---------------- epilogue ----------------
    const int r  = lane >> 2;
    const int cq = (lane & 3) * 2;
#pragma unroll
    for (int i = 0; i < 4; i++) {
#pragma unroll
        for (int j = 0; j < 4; j++) {
            const int col = n0 + warp_col + j * 8 + cq;
            const int row0 = m0 + warp_row + i * 16 + r;
            const int row1 = row0 + 8;
            float2 v0, v1;
            v0.x = acc[i][j][0] * alpha; v0.y = acc[i][j][1] * alpha;
            v1.x = acc[i][j][2] * alpha; v1.y = acc[i][j][3] * alpha;
            if (CAUSAL) {
                if (col     > row0) v0.x = -1e30f;
                if (col + 1 > row0) v0.y = -1e30f;
                if (col     > row1) v1.x = -1e30f;
                if (col + 1 > row1) v1.y = -1e30f;
            }
            *(float2*)(C + (long)row0 * ldc + col) = v0;
            *(float2*)(C + (long)row1 * ldc + col) = v1;
        }
    }
}

// ---------------- warp reductions ------------------------------------------
__device__ __forceinline__ float warp_sum(float v) {
#pragma unroll
    for (int o = 16; o; o >>= 1) v += __shfl_xor_sync(0xffffffffu, v, o);
    return v;
}
__device__ __forceinline__ float warp_max(float v) {
#pragma unroll
    for (int o = 16; o; o >>= 1) v = fmaxf(v, __shfl_xor_sync(0xffffffffu, v, o));
    return v;
}

// ---------------- RoPE tables (fp64, once) ----------------------------------
__global__ void __launch_bounds__(256)
rope_tables(const int* __restrict__ pos) {
    const int i = blockIdx.x * 256 + threadIdx.x;     // SEQ*128 threads
    const int s = i >> 7, fi = i & 127;
    const double inv = exp(-(double)fi * (9.210340371976184 / 128.0));
    const double ang = (double)pos[s] * inv;
    g_sin[i] = (float)sin(ang);
    g_cos[i] = (float)cos(ang);
}

// ---------------- fused RMSNorm + RoPE (one block per (h,s,b)) --------------
__global__ void __launch_bounds__(HDIM)
rmsnorm_rope(float* __restrict__ X, const float* __restrict__ w)
{
    const int h = blockIdx.x, s = blockIdx.y, b = blockIdx.z, t = threadIdx.x;
    __shared__ float buf[HDIM];
    __shared__ float red[8];

    const int half = HDIM / 2;
    const int fi = (t < half) ? t : t - half;
    const float cs = g_cos[s * half + fi];
    const float sn = g_sin[s * half + fi];

    float* v = X + ((long)(b * SEQ + s)) * EDIM + h * HDIM;
    const float x = v[t];
    const int wid = t >> 5, lane = t & 31;

    float ss = warp_sum(x * x);
    if (lane == 0) red[wid] = ss;
    __syncthreads();
    float tot = 0.f;
#pragma unroll
    for (int rr = 0; rr < 8; rr++) tot += red[rr];

    const float xn = x * rsqrtf(tot * (1.0f / HDIM) + 1e-6f) * w[t];
    buf[t] = xn;
    __syncthreads();

    float out;
    if (t < half) out = xn * cs - buf[t + half] * sn;
    else          out = xn * cs + buf[t - half] * sn;
    v[t] = out;
}

// ---------------- V transpose: per (b,h)  Vt[d][s] = V[s][d] -----------------
__global__ void __launch_bounds__(256)
transpose_v(const float* __restrict__ V, float* __restrict__ Vt)
{
    __shared__ float tile[32][33];
    const int bh = blockIdx.z;
    const int b = bh / NHEAD, h = bh % NHEAD;
    const int s0 = blockIdx.x * 32, d0 = blockIdx.y * 32;
    const int tx = threadIdx.x & 31, ty = threadIdx.x >> 5;   // 32 x 8

    const float* src = V + (long)b * SEQ * EDIM + h * HDIM;
#pragma unroll
    for (int i = ty; i < 32; i += 8)
        tile[i][tx] = src[(long)(s0 + i) * EDIM + d0 + tx];
    __syncthreads();
    float* dst = Vt + ((long)bh * HDIM + d0) * SEQ + s0;
#pragma unroll
    for (int i = ty; i < 32; i += 8)
        dst[(long)i * SEQ + tx] = tile[tx][i];
}

// ---------------- causal row softmax (in place) ------------------------------
__global__ void __launch_bounds__(256)
softmax_causal(float* __restrict__ Sc)
{
    const int q  = blockIdx.x;
    const int bh = blockIdx.y;
    float* row = Sc + ((long)bh * SEQ + q) * SEQ;
    const int W = (((q >> 7) + 1) << 7);

    const int tid = threadIdx.x;
    const int wid = tid >> 5, lane = tid & 31;
    __shared__ float red[8];

    float x[8];
    float m = -1e30f;
#pragma unroll
    for (int i = 0; i < 8; i++) {
        const int idx = tid + i * 256;
        x[i] = (idx < W) ? row[idx] : -1e30f;
        m = fmaxf(m, x[i]);
    }
    m = warp_max(m);
    if (lane == 0) red[wid] = m;
    __syncthreads();
    float M = -1e30f;
#pragma unroll
    for (int rr = 0; rr < 8; rr++) M = fmaxf(M, red[rr]);

    float ssum = 0.f;
#pragma unroll
    for (int i = 0; i < 8; i++) { x[i] = __expf(x[i] - M); ssum += x[i]; }
    ssum = warp_sum(ssum);
    __syncthreads();
    if (lane == 0) red[wid] = ssum;
    __syncthreads();
    float tot = 0.f;
#pragma unroll
    for (int rr = 0; rr < 8; rr++) tot += red[rr];
    const float invs = 1.0f / tot;

#pragma unroll
    for (int i = 0; i < 8; i++) {
        const int idx = tid + i * 256;
        if (idx < W) row[idx] = x[i] * invs;
    }
}

// ---------------- launcher ---------------------------------------------------
extern "C" void kernel_launch(void* const* d_in, const int* in_sizes, int n_in,
                              void* d_out, int out_size)
{
    const float* x   = (const float*)d_in[0];
    const int*   pos = (const int*)  d_in[1];
    const float* Wq  = (const float*)d_in[2];
    const float* Wk  = (const float*)d_in[3];
    const float* Wv  = (const float*)d_in[4];
    const float* Wo  = (const float*)d_in[5];
    const float* qw  = (const float*)d_in[6];
    const float* kw  = (const float*)d_in[7];
    float* out = (float*)d_out;

    float *Q, *K, *V, *Vt, *O, *Sc;
    cudaGetSymbolAddress((void**)&Q,  g_Q);
    cudaGetSymbolAddress((void**)&K,  g_K);
    cudaGetSymbolAddress((void**)&V,  g_V);
    cudaGetSymbolAddress((void**)&Vt, g_Vt);
    cudaGetSymbolAddress((void**)&O,  g_O);
    cudaGetSymbolAddress((void**)&Sc, g_S);

    const dim3 blk(256);
    const long SS = (long)SEQ * SEQ;

    rope_tables<<<(SEQ * (HDIM / 2)) / 256, 256>>>(pos);

    // 1) QKV projections: [4096 x 2048] = [4096 x 2048] * [2048 x 2048]^T
    const dim3 g1(EDIM / BN, MROWS / BM, 1);
    gemm_tc<false, false><<<g1, blk>>>(x, Wq, Q, DIM, DIM, DIM, EDIM,
        1, 0, 0, 0, 0, 0, 0, 1.0f);
    gemm_tc<false, false><<<g1, blk>>>(x, Wk, K, DIM, DIM, DIM, EDIM,
        1, 0, 0, 0, 0, 0, 0, 1.0f);
    gemm_tc<false, false><<<g1, blk>>>(x, Wv, V, DIM, DIM, DIM, EDIM,
        1, 0, 0, 0, 0, 0, 0, 1.0f);

    // 2) RMSNorm + RoPE on Q and K
    rmsnorm_rope<<<dim3(NHEAD, SEQ, BATCH), HDIM>>>(Q, qw);
    rmsnorm_rope<<<dim3(NHEAD, SEQ, BATCH), HDIM>>>(K, kw);

    // 2b) transpose V per head -> Vt [bh][d][s]
    transpose_v<<<dim3(SEQ / 32, HDIM / 32, BATCH * NHEAD), 256>>>(V, Vt);

    // 3) scores = Q K^T * scale (causal-masked, upper blocks skipped)
    const dim3 g2(SEQ / BN, SEQ / BM, BATCH * NHEAD);
    gemm_tc<true, false><<<g2, blk>>>(Q, K, Sc, HDIM, EDIM, EDIM, SEQ,
        NHEAD, (long)SEQ * EDIM, HDIM, (long)SEQ * EDIM, HDIM,
        (long)NHEAD * SS, SS, 0.0625f);

    // 4) causal softmax (in place)
    softmax_causal<<<dim3(SEQ, BATCH * NHEAD), blk>>>(Sc);

    // 5) O = P V   (K-limited to m0+128 per row-block)
    const dim3 g3(HDIM / BN, SEQ / BM, BATCH * NHEAD);
    gemm_tc<false, true><<<g3, blk>>>(Sc, Vt, O, SEQ, SEQ, SEQ, EDIM,
        NHEAD, (long)NHEAD * SS, SS,
        (long)NHEAD * HDIM * SEQ, (long)HDIM * SEQ,
        (long)SEQ * EDIM, HDIM, 1.0f);

    // 6) out = O Wo^T
    gemm_tc<false, false><<<g1, blk>>>(O, Wo, out, EDIM, EDIM, EDIM, DIM,
        1, 0, 0, 0, 0, 0, 0, 1.0f);
}

// round 5
// speedup vs baseline: 2.6448x; 1.0526x over previous
#include <cuda_runtime.h>
#include <cuda_bf16.h>
#include <math.h>
#include <stdint.h>

#define BATCH 2
#define SEQ   2048
#define DIM   2048
#define NHEAD 8
#define HDIM  256
#define EDIM  (NHEAD * HDIM)   // 2048
#define MROWS (BATCH * SEQ)    // 4096

// ---------------- scratch (device globals; no cudaMalloc allowed) ----------
__device__ float g_Q [(size_t)MROWS * EDIM];
__device__ float g_K [(size_t)MROWS * EDIM];
__device__ float g_V [(size_t)MROWS * EDIM];
__device__ float g_S [(size_t)BATCH * NHEAD * SEQ * SEQ];   // 268 MB scores
__device__ float g_sin[SEQ * (HDIM / 2)];
__device__ float g_cos[SEQ * (HDIM / 2)];

// bf16 hi/lo operand pairs
__device__ __nv_bfloat16 g_xh [(size_t)MROWS * DIM],  g_xl [(size_t)MROWS * DIM];
__device__ __nv_bfloat16 g_Wqh[(size_t)EDIM * DIM],   g_Wql[(size_t)EDIM * DIM];
__device__ __nv_bfloat16 g_Wkh[(size_t)EDIM * DIM],   g_Wkl[(size_t)EDIM * DIM];
__device__ __nv_bfloat16 g_Wvh[(size_t)EDIM * DIM],   g_Wvl[(size_t)EDIM * DIM];
__device__ __nv_bfloat16 g_Woh[(size_t)DIM * EDIM],   g_Wol[(size_t)DIM * EDIM];
__device__ __nv_bfloat16 g_Qh [(size_t)MROWS * EDIM], g_Ql [(size_t)MROWS * EDIM];
__device__ __nv_bfloat16 g_Kh [(size_t)MROWS * EDIM], g_Kl [(size_t)MROWS * EDIM];
__device__ __nv_bfloat16 g_Vth[(size_t)MROWS * EDIM], g_Vtl[(size_t)MROWS * EDIM];
__device__ __nv_bfloat16 g_Oh [(size_t)MROWS * EDIM], g_Ol [(size_t)MROWS * EDIM];
__device__ __nv_bfloat16 g_Ph [(size_t)BATCH * NHEAD * SEQ * SEQ];
__device__ __nv_bfloat16 g_Pl [(size_t)BATCH * NHEAD * SEQ * SEQ];

// ---------------- helpers ----------------------------------------------------
__device__ __forceinline__ uint32_t s2u(const void* p) {
    return (uint32_t)__cvta_generic_to_shared(p);
}
__device__ __forceinline__ void cpa16(uint32_t s, const void* g) {
    asm volatile("cp.async.cg.shared.global [%0], [%1], 16;" :: "r"(s), "l"(g));
}
#define CP_COMMIT() asm volatile("cp.async.commit_group;" ::: "memory")
#define CP_WAIT1()  asm volatile("cp.async.wait_group 1;" ::: "memory")

// split two floats -> hi bf16x2 + residual lo bf16x2 (x in low 16 bits)
__device__ __forceinline__ void pack_split(float2 f, uint32_t& hi, uint32_t& lo) {
    uint32_t h;
    asm("cvt.rn.bf16x2.f32 %0, %1, %2;" : "=r"(h) : "f"(f.y), "f"(f.x));
    float fyh = __uint_as_float(h & 0xffff0000u);
    float fxh = __uint_as_float(h << 16);
    asm("cvt.rn.bf16x2.f32 %0, %1, %2;" : "=r"(lo) : "f"(f.y - fyh), "f"(f.x - fxh));
    hi = h;
}

__device__ __forceinline__ void mma16816(float* c, const uint32_t* a, const uint32_t* b) {
    asm volatile("mma.sync.aligned.m16n8k16.row.col.f32.bf16.bf16.f32 "
        "{%0,%1,%2,%3},{%4,%5,%6,%7},{%8,%9},{%0,%1,%2,%3};"
        : "+f"(c[0]), "+f"(c[1]), "+f"(c[2]), "+f"(c[3])
        : "r"(a[0]), "r"(a[1]), "r"(a[2]), "r"(a[3]), "r"(b[0]), "r"(b[1]));
}

#define LDSM4(R, addr)                                                          \
    asm volatile("ldmatrix.sync.aligned.m8n8.x4.shared.b16 {%0,%1,%2,%3}, [%4];"\
        : "=r"((R)[0]), "=r"((R)[1]), "=r"((R)[2]), "=r"((R)[3]) : "r"(addr))

// swizzle inside a 128x16 bf16 subtile stored as 16B chunks (row, half-of-k16)
__device__ __forceinline__ uint32_t chunkoff(int row, int half) {
    const int line = row >> 2;
    const int cp = ((row & 3) << 1) | half;
    return (uint32_t)(line * 128 + ((cp ^ (line & 7)) << 4));
}

// ---------------- bf16x3-split tensor-core GEMM ------------------------------
// C[m][n] = alpha * sum_k (Ah+Al)[m][k] * (Bh+Bl)[n][k]  (bf16 K-major, lo*lo dropped)
#define BM 128
#define BN 128
#define BK 32
#define NS 3
#define T_AHI 0
#define T_ALO 8192
#define T_BHI 16384
#define T_BLO 24576
#define STG   32768
#define GEMM_SMEM (NS * STG)     // 98304

template<bool CAUSAL, bool CAUSAL_K, bool OSPLIT>
__global__ void __launch_bounds__(256, 2)
gemm_bf3(const __nv_bfloat16* __restrict__ Ahg, const __nv_bfloat16* __restrict__ Alg,
         const __nv_bfloat16* __restrict__ Bhg, const __nv_bfloat16* __restrict__ Blg,
         float* __restrict__ Cg, __nv_bfloat16* __restrict__ Chg, __nv_bfloat16* __restrict__ Clg,
         int K, int lda, int ldb, int ldc, int batch_inner,
         long sa_out, long sa_in, long sb_out, long sb_in,
         long sc_out, long sc_in, float alpha)
{
    const int m0 = blockIdx.y * BM;
    const int n0 = blockIdx.x * BN;
    if (CAUSAL && n0 > m0 + BM - 1) return;

    const int z = blockIdx.z, zo = z / batch_inner, zi = z % batch_inner;
    const __nv_bfloat16* Ah = Ahg + zo * sa_out + zi * sa_in + (long)m0 * lda;
    const __nv_bfloat16* Al = Alg + zo * sa_out + zi * sa_in + (long)m0 * lda;
    const __nv_bfloat16* Bh = Bhg + zo * sb_out + zi * sb_in + (long)n0 * ldb;
    const __nv_bfloat16* Bl = Blg + zo * sb_out + zi * sb_in + (long)n0 * ldb;

    extern __shared__ __align__(128) char smem[];
    const uint32_t sbase = s2u(smem);

    const int tid = threadIdx.x, wid = tid >> 5, lane = tid & 31;
    const int wm = wid >> 2, wn = wid & 3;           // warp grid 2 x 4
    const int warp_row = wm * 64, warp_col = wn * 32;

    int kend = K;
    if (CAUSAL_K) { int ke = m0 + BM; kend = ke < K ? ke : K; }
    const int nk = kend / BK;

    // ldmatrix geometry (sub-tile 0 offsets; sub 1 adds 4096)
    const int mat = lane >> 3;
    const int lrow = ((mat & 1) << 3) | (lane & 7);
    const int lhalf = mat >> 1;
    uint32_t aoff[4];
#pragma unroll
    for (int i = 0; i < 4; i++)
        aoff[i] = chunkoff(warp_row + i * 16 + lrow, lhalf);
    const int bj = mat >> 1, bhh = mat & 1;
    const uint32_t boff0 = chunkoff(warp_col + bj * 8 + (lane & 7), bhh);
    const uint32_t boff1 = chunkoff(warp_col + 16 + bj * 8 + (lane & 7), bhh);

    // cp.async geometry: 2 chunks per thread per tile-part
    auto load_stage = [&](int stage) {
        if (stage >= nk) return;
        const uint32_t s0 = sbase + (stage % NS) * STG;
        const long k0 = (long)stage * BK;
#pragma unroll
        for (int j = 0; j < 2; j++) {
            const int c = tid + j * 256;            // 0..511
            const int row = c >> 2, sub = (c >> 1) & 1, half = c & 1;
            const uint32_t doff = sub * 4096 + chunkoff(row, half);
            const long goff = k0 + sub * 16 + half * 8;
            cpa16(s0 + T_AHI + doff, Ah + (long)row * lda + goff);
            cpa16(s0 + T_ALO + doff, Al + (long)row * lda + goff);
            cpa16(s0 + T_BHI + doff, Bh + (long)row * ldb + goff);
            cpa16(s0 + T_BLO + doff, Bl + (long)row * ldb + goff);
        }
    };

    float acc[4][4][4];
#pragma unroll
    for (int i = 0; i < 4; i++)
#pragma unroll
        for (int j = 0; j < 4; j++)
#pragma unroll
            for (int e = 0; e < 4; e++) acc[i][j][e] = 0.f;

    load_stage(0); CP_COMMIT();
    load_stage(1); CP_COMMIT();

    for (int it = 0; it < nk; it++) {
        CP_WAIT1();
        __syncthreads();
        const uint32_t s0 = sbase + (it % NS) * STG;
#pragma unroll
        for (int sub = 0; sub < 2; sub++) {
            const uint32_t so = s0 + sub * 4096;
            uint32_t bhr[8], blr[8];
            LDSM4(bhr + 0, so + T_BHI + boff0);
            LDSM4(bhr + 4, so + T_BHI + boff1);
            LDSM4(blr + 0, so + T_BLO + boff0);
            LDSM4(blr + 4, so + T_BLO + boff1);
#pragma unroll
            for (int i = 0; i < 4; i++) {
                uint32_t ah[4], al[4];
                LDSM4(ah, so + T_AHI + aoff[i]);
                LDSM4(al, so + T_ALO + aoff[i]);
#pragma unroll
                for (int j = 0; j < 4; j++) {
                    mma16816(acc[i][j], ah, &bhr[j * 2]);   // hi*hi
                    mma16816(acc[i][j], ah, &blr[j * 2]);   // hi*lo
                    mma16816(acc[i][j], al, &bhr[j * 2]);   // lo*hi
                }
            }
        }
        load_stage(it + 2);      // writes slot (it+2)%3 != slots being read
        CP_COMMIT();
    }

    // ---------------- epilogue ----------------
    const int r  = lane >> 2;
    const int cq = (lane & 3) * 2;
    float* C = OSPLIT ? nullptr : (Cg + zo * sc_out + zi * sc_in);
    __nv_bfloat16* Ch = OSPLIT ? (Chg + zo * sc_out + zi * sc_in) : nullptr;
    __nv_bfloat16* Cl = OSPLIT ? (Clg + zo * sc_out + zi * sc_in) : nullptr;
#pragma unroll
    for (int i = 0; i < 4; i++) {
#pragma unroll
        for (int j = 0; j < 4; j++) {
            const int col = n0 + warp_col + j * 8 + cq;
            const int row0 = m0 + warp_row + i * 16 + r;
            const int row1 = row0 + 8;
            float2 v0, v1;
            v0.x = acc[i][j][0] * alpha; v0.y = acc[i][j][1] * alpha;
            v1.x = acc[i][j][2] * alpha; v1.y = acc[i][j][3] * alpha;
            if (CAUSAL) {
                if (col     > row0) v0.x = -1e30f;
                if (col + 1 > row0) v0.y = -1e30f;
                if (col     > row1) v1.x = -1e30f;
                if (col + 1 > row1) v1.y = -1e30f;
            }
            if (OSPLIT) {
                uint32_t h0, l0, h1, l1;
                pack_split(v0, h0, l0);
                pack_split(v1, h1, l1);
                *(uint32_t*)(Ch + (long)row0 * ldc + col) = h0;
                *(uint32_t*)(Cl + (long)row0 * ldc + col) = l0;
                *(uint32_t*)(Ch + (long)row1 * ldc + col) = h1;
                *(uint32_t*)(Cl + (long)row1 * ldc + col) = l1;
            } else {
                *(float2*)(C + (long)row0 * ldc + col) = v0;
                *(float2*)(C + (long)row1 * ldc + col) = v1;
            }
        }
    }
}

// ---------------- fp32 -> bf16 hi/lo split (vectorized) ----------------------
__global__ void __launch_bounds__(256)
split_fp32(const float* __restrict__ src, __nv_bfloat16* __restrict__ hi,
           __nv_bfloat16* __restrict__ lo, int n4)
{
    const int i = blockIdx.x * 256 + threadIdx.x;
    if (i >= n4) return;
    const float4 v = ((const float4*)src)[i];
    uint32_t h0, l0, h1, l1;
    pack_split(make_float2(v.x, v.y), h0, l0);
    pack_split(make_float2(v.z, v.w), h1, l1);
    ((uint2*)hi)[i] = make_uint2(h0, h1);
    ((uint2*)lo)[i] = make_uint2(l0, l1);
}

// ---------------- warp reductions ------------------------------------------
__device__ __forceinline__ float warp_sum(float v) {
#pragma unroll
    for (int o = 16; o; o >>= 1) v += __shfl_xor_sync(0xffffffffu, v, o);
    return v;
}
__device__ __forceinline__ float warp_max(float v) {
#pragma unroll
    for (int o = 16; o; o >>= 1) v = fmaxf(v, __shfl_xor_sync(0xffffffffu, v, o));
    return v;
}

// ---------------- RoPE tables (fp64, once) ----------------------------------
__global__ void __launch_bounds__(256)
rope_tables(const int* __restrict__ pos) {
    const int i = blockIdx.x * 256 + threadIdx.x;
    const int s = i >> 7, fi = i & 127;
    const double inv = exp(-(double)fi * (9.210340371976184 / 128.0));
    const double ang = (double)pos[s] * inv;
    g_sin[i] = (float)sin(ang);
    g_cos[i] = (float)cos(ang);
}

// ---------------- fused RMSNorm + RoPE -> bf16 hi/lo -------------------------
__global__ void __launch_bounds__(HDIM)
rmsnorm_rope_split(const float* __restrict__ X, const float* __restrict__ w,
                   __nv_bfloat16* __restrict__ Xh, __nv_bfloat16* __restrict__ Xl)
{
    const int h = blockIdx.x, s = blockIdx.y, b = blockIdx.z, t = threadIdx.x;
    __shared__ float buf[HDIM];
    __shared__ float red[8];

    const int half = HDIM / 2;
    const int fi = (t < half) ? t : t - half;
    const float cs = g_cos[s * half + fi];
    const float sn = g_sin[s * half + fi];

    const long idx = ((long)(b * SEQ + s)) * EDIM + h * HDIM + t;
    const float x = X[idx];
    const int wid = t >> 5, lane = t & 31;

    float ss = warp_sum(x * x);
    if (lane == 0) red[wid] = ss;
    __syncthreads();
    float tot = 0.f;
#pragma unroll
    for (int rr = 0; rr < 8; rr++) tot += red[rr];

    const float xn = x * rsqrtf(tot * (1.0f / HDIM) + 1e-6f) * w[t];
    buf[t] = xn;
    __syncthreads();

    float out;
    if (t < half) out = xn * cs - buf[t + half] * sn;
    else          out = xn * cs + buf[t - half] * sn;

    const __nv_bfloat16 oh = __float2bfloat16(out);
    Xh[idx] = oh;
    Xl[idx] = __float2bfloat16(out - __bfloat162float(oh));
}

// ---------------- V transpose -> bf16 hi/lo  Vt[bh][d][s] --------------------
__global__ void __launch_bounds__(256)
transpose_v_split(const float* __restrict__ V,
                  __nv_bfloat16* __restrict__ Vth, __nv_bfloat16* __restrict__ Vtl)
{
    __shared__ float tile[32][33];
    const int bh = blockIdx.z;
    const int b = bh / NHEAD, h = bh % NHEAD;
    const int s0 = blockIdx.x * 32, d0 = blockIdx.y * 32;
    const int tx = threadIdx.x & 31, ty = threadIdx.x >> 5;

    const float* src = V + (long)b * SEQ * EDIM + h * HDIM;
#pragma unroll
    for (int i = ty; i < 32; i += 8)
        tile[i][tx] = src[(long)(s0 + i) * EDIM + d0 + tx];
    __syncthreads();
    const long dbase = ((long)bh * HDIM + d0) * SEQ + s0;
#pragma unroll
    for (int i = ty; i < 32; i += 8) {
        const float v = tile[tx][i];
        const __nv_bfloat16 vh = __float2bfloat16(v);
        Vth[dbase + (long)i * SEQ + tx] = vh;
        Vtl[dbase + (long)i * SEQ + tx] = __float2bfloat16(v - __bfloat162float(vh));
    }
}

// ---------------- causal row softmax -> bf16 hi/lo ---------------------------
__global__ void __launch_bounds__(256)
softmax_causal_split(const float* __restrict__ Sc,
                     __nv_bfloat16* __restrict__ Ph, __nv_bfloat16* __restrict__ Pl)
{
    const int q  = blockIdx.x;
    const int bh = blockIdx.y;
    const long rb = ((long)bh * SEQ + q) * SEQ;
    const float* row = Sc + rb;
    const int W = (((q >> 7) + 1) << 7);

    const int tid = threadIdx.x;
    const int wid = tid >> 5, lane = tid & 31;
    __shared__ float red[8];

    float x[8];
    float m = -1e30f;
#pragma unroll
    for (int i = 0; i < 8; i++) {
        const int idx = tid + i * 256;
        x[i] = (idx < W) ? row[idx] : -1e30f;
        m = fmaxf(m, x[i]);
    }
    m = warp_max(m);
    if (lane == 0) red[wid] = m;
    __syncthreads();
    float M = -1e30f;
#pragma unroll
    for (int rr = 0; rr < 8; rr++) M = fmaxf(M, red[rr]);

    float ssum = 0.f;
#pragma unroll
    for (int i = 0; i < 8; i++) { x[i] = __expf(x[i] - M); ssum += x[i]; }
    ssum = warp_sum(ssum);
    __syncthreads();
    if (lane == 0) red[wid] = ssum;
    __syncthreads();
    float tot = 0.f;
#pragma unroll
    for (int rr = 0; rr < 8; rr++) tot += red[rr];
    const float invs = 1.0f / tot;

#pragma unroll
    for (int i = 0; i < 8; i++) {
        const int idx = tid + i * 256;
        if (idx < W) {
            const float p = x[i] * invs;
            const __nv_bfloat16 ph = __float2bfloat16(p);
            Ph[rb + idx] = ph;
            Pl[rb + idx] = __float2bfloat16(p - __bfloat162float(ph));
        }
    }
}

// ---------------- launcher ---------------------------------------------------
extern "C" void kernel_launch(void* const* d_in, const int* in_sizes, int n_in,
                              void* d_out, int out_size)
{
    const float* x   = (const float*)d_in[0];
    const int*   pos = (const int*)  d_in[1];
    const float* Wq  = (const float*)d_in[2];
    const float* Wk  = (const float*)d_in[3];
    const float* Wv  = (const float*)d_in[4];
    const float* Wo  = (const float*)d_in[5];
    const float* qw  = (const float*)d_in[6];
    const float* kw  = (const float*)d_in[7];
    float* out = (float*)d_out;

    float *Q, *K, *V, *Sc, *dummyf = nullptr;
    cudaGetSymbolAddress((void**)&Q,  g_Q);
    cudaGetSymbolAddress((void**)&K,  g_K);
    cudaGetSymbolAddress((void**)&V,  g_V);
    cudaGetSymbolAddress((void**)&Sc, g_S);

    __nv_bfloat16 *xh, *xl, *Wqh, *Wql, *Wkh, *Wkl, *Wvh, *Wvl, *Woh, *Wol;
    __nv_bfloat16 *Qh, *Ql, *Kh, *Kl, *Vth, *Vtl, *Oh, *Ol, *Ph, *Pl;
    cudaGetSymbolAddress((void**)&xh,  g_xh);  cudaGetSymbolAddress((void**)&xl,  g_xl);
    cudaGetSymbolAddress((void**)&Wqh, g_Wqh); cudaGetSymbolAddress((void**)&Wql, g_Wql);
    cudaGetSymbolAddress((void**)&Wkh, g_Wkh); cudaGetSymbolAddress((void**)&Wkl, g_Wkl);
    cudaGetSymbolAddress((void**)&Wvh, g_Wvh); cudaGetSymbolAddress((void**)&Wvl, g_Wvl);
    cudaGetSymbolAddress((void**)&Woh, g_Woh); cudaGetSymbolAddress((void**)&Wol, g_Wol);
    cudaGetSymbolAddress((void**)&Qh,  g_Qh);  cudaGetSymbolAddress((void**)&Ql,  g_Ql);
    cudaGetSymbolAddress((void**)&Kh,  g_Kh);  cudaGetSymbolAddress((void**)&Kl,  g_Kl);
    cudaGetSymbolAddress((void**)&Vth, g_Vth); cudaGetSymbolAddress((void**)&Vtl, g_Vtl);
    cudaGetSymbolAddress((void**)&Oh,  g_Oh);  cudaGetSymbolAddress((void**)&Ol,  g_Ol);
    cudaGetSymbolAddress((void**)&Ph,  g_Ph);  cudaGetSymbolAddress((void**)&Pl,  g_Pl);

    cudaFuncSetAttribute(gemm_bf3<false, false, false>,
        cudaFuncAttributeMaxDynamicSharedMemorySize, GEMM_SMEM);
    cudaFuncSetAttribute(gemm_bf3<true, false, false>,
        cudaFuncAttributeMaxDynamicSharedMemorySize, GEMM_SMEM);
    cudaFuncSetAttribute(gemm_bf3<false, true, true>,
        cudaFuncAttributeMaxDynamicSharedMemorySize, GEMM_SMEM);

    const dim3 blk(256);
    const long SS = (long)SEQ * SEQ;

    rope_tables<<<(SEQ * (HDIM / 2)) / 256, 256>>>(pos);

    // 0) split fp32 inputs into bf16 hi/lo
    split_fp32<<<(MROWS * DIM / 4) / 256, 256>>>(x,  xh,  xl,  MROWS * DIM / 4);
    split_fp32<<<(EDIM * DIM / 4) / 256, 256>>>(Wq, Wqh, Wql, EDIM * DIM / 4);
    split_fp32<<<(EDIM * DIM / 4) / 256, 256>>>(Wk, Wkh, Wkl, EDIM * DIM / 4);
    split_fp32<<<(EDIM * DIM / 4) / 256, 256>>>(Wv, Wvh, Wvl, EDIM * DIM / 4);
    split_fp32<<<(DIM * EDIM / 4) / 256, 256>>>(Wo, Woh, Wol, DIM * EDIM / 4);

    // 1) QKV projections (fp32 out)
    const dim3 g1(EDIM / BN, MROWS / BM, 1);
    gemm_bf3<false, false, false><<<g1, blk, GEMM_SMEM>>>(xh, xl, Wqh, Wql,
        Q, nullptr, nullptr, DIM, DIM, DIM, EDIM, 1, 0, 0, 0, 0, 0, 0, 1.0f);
    gemm_bf3<false, false, false><<<g1, blk, GEMM_SMEM>>>(xh, xl, Wkh, Wkl,
        K, nullptr, nullptr, DIM, DIM, DIM, EDIM, 1, 0, 0, 0, 0, 0, 0, 1.0f);
    gemm_bf3<false, false, false><<<g1, blk, GEMM_SMEM>>>(xh, xl, Wvh, Wvl,
        V, nullptr, nullptr, DIM, DIM, DIM, EDIM, 1, 0, 0, 0, 0, 0, 0, 1.0f);

    // 2) RMSNorm + RoPE -> bf16 hi/lo
    rmsnorm_rope_split<<<dim3(NHEAD, SEQ, BATCH), HDIM>>>(Q, qw, Qh, Ql);
    rmsnorm_rope_split<<<dim3(NHEAD, SEQ, BATCH), HDIM>>>(K, kw, Kh, Kl);

    // 2b) transpose V -> bf16 hi/lo  [bh][d][s]
    transpose_v_split<<<dim3(SEQ / 32, HDIM / 32, BATCH * NHEAD), 256>>>(V, Vth, Vtl);

    // 3) scores = Q K^T * scale (causal-masked, upper blocks skipped)
    const dim3 g2(SEQ / BN, SEQ / BM, BATCH * NHEAD);
    gemm_bf3<true, false, false><<<g2, blk, GEMM_SMEM>>>(Qh, Ql, Kh, Kl,
        Sc, nullptr, nullptr, HDIM, EDIM, EDIM, SEQ,
        NHEAD, (long)SEQ * EDIM, HDIM, (long)SEQ * EDIM, HDIM,
        (long)NHEAD * SS, SS, 0.0625f);

    // 4) causal softmax -> P bf16 hi/lo
    softmax_causal_split<<<dim3(SEQ, BATCH * NHEAD), blk>>>(Sc, Ph, Pl);

    // 5) O = P V  (K-limited to m0+128), output split to bf16 hi/lo
    const dim3 g3(HDIM / BN, SEQ / BM, BATCH * NHEAD);
    gemm_bf3<false, true, true><<<g3, blk, GEMM_SMEM>>>(Ph, Pl, Vth, Vtl,
        dummyf, Oh, Ol, SEQ, SEQ, SEQ, EDIM,
        NHEAD, (long)NHEAD * SS, SS,
        (long)NHEAD * HDIM * SEQ, (long)HDIM * SEQ,
        (long)SEQ * EDIM, HDIM, 1.0f);

    // 6) out = O Wo^T (fp32 out)
    gemm_bf3<false, false, false><<<g1, blk, GEMM_SMEM>>>(Oh, Ol, Woh, Wol,
        out, nullptr, nullptr, EDIM, EDIM, EDIM, DIM, 1, 0, 0, 0, 0, 0, 0, 1.0f);
}